// round 14
// baseline (speedup 1.0000x reference)
#include <cuda_runtime.h>
#include <cuda_fp16.h>
#include <cstdint>

// Problem shape (fixed): B=2, S=2048, D=2048, H=16, DK=128
constexpr int BATCH  = 2;
constexpr int SEQ    = 2048;
constexpr int DMODEL = 2048;
constexpr int NH     = 16;
constexpr int HD     = 128;
constexpr int QKVW   = 3 * DMODEL;   // 6144
constexpr int BH     = BATCH * NH;   // 32

// q pre-scale: 1/sqrt(128) * log2(e)  (folded so softmax uses bare exp2)
constexpr float QS2 = 0.08838834764831845f * 1.4426950408889634f;

// ---------------------------------------------------------------------------
// Scratch (device globals — allocation-free per harness rules)
// ---------------------------------------------------------------------------
__device__ __half g_xsHi [(long)BATCH * SEQ * DMODEL];
__device__ __half g_wqHi [(long)QKVW * DMODEL];
__device__ __half g_woHi [(long)DMODEL * DMODEL];
__device__ __half g_qkvHi[(long)BATCH * SEQ * QKVW];
__device__ __half g_vtHi [(long)BH * HD * SEQ];
__device__ __half g_atHi [(long)BATCH * SEQ * DMODEL];

// ---------------------------------------------------------------------------
// helpers
// ---------------------------------------------------------------------------
__device__ __forceinline__ uint32_t smem_u32(const void* p) {
    uint32_t a;
    asm("{ .reg .u64 t; cvta.to.shared.u64 t, %1; cvt.u32.u64 %0, t; }"
        : "=r"(a) : "l"(p));
    return a;
}
__device__ __forceinline__ void cp16(uint32_t saddr, const void* g) {
    asm volatile("cp.async.cg.shared.global [%0], [%1], 16;" :: "r"(saddr), "l"(g));
}
#define CP_COMMIT() asm volatile("cp.async.commit_group;" ::: "memory")
#define CP_WAIT2()  asm volatile("cp.async.wait_group 2;" ::: "memory")
#define CP_WAIT1()  asm volatile("cp.async.wait_group 1;" ::: "memory")
#define CP_WAIT0()  asm volatile("cp.async.wait_group 0;" ::: "memory")

__device__ __forceinline__ void ldsm_x4(uint32_t addr, uint32_t& r0, uint32_t& r1,
                                        uint32_t& r2, uint32_t& r3) {
    asm volatile("ldmatrix.sync.aligned.m8n8.x4.shared.b16 {%0,%1,%2,%3}, [%4];"
                 : "=r"(r0), "=r"(r1), "=r"(r2), "=r"(r3) : "r"(addr));
}
__device__ __forceinline__ void mma_f16(float* c, const uint32_t* a, const uint32_t* b) {
    asm volatile(
        "mma.sync.aligned.m16n8k16.row.col.f32.f16.f16.f32 "
        "{%0,%1,%2,%3}, {%4,%5,%6,%7}, {%8,%9}, {%0,%1,%2,%3};"
        : "+f"(c[0]), "+f"(c[1]), "+f"(c[2]), "+f"(c[3])
        : "r"(a[0]), "r"(a[1]), "r"(a[2]), "r"(a[3]), "r"(b[0]), "r"(b[1]));
}
__device__ __forceinline__ uint32_t trunc2h(float v0, float v1) {
    __half2 t = __floats2half2_rn(v0, v1);   // single F2FP.PACK instruction
    return *(uint32_t*)&t;
}

// ---------------------------------------------------------------------------
// HMMA GEMM (pure fp16): C[m,n] = sum_k Ah[m,k] * Bh[n,k]  (NT)
// CTA tile 128x128, BK=64, 3-stage cp.async (1 sync/iter, prefetch at bottom).
// 8 warps (2x4), warp tile 64x32. 144B padded rows. 2 CTAs/SM.
// QSC: multiply q-tiles (blockIdx.x%3==0) by QS2 after bias (exp2 folding).
// ---------------------------------------------------------------------------
constexpr int ROWB_G  = 144;              // 64 fp16 = 128B data + 16B pad
constexpr int MAT_G   = 128 * ROWB_G;     // 18432
constexpr int STAGE_G = 2 * MAT_G;        // Ah, Bh = 36864
constexpr int SMEM_G  = 3 * STAGE_G;      // 110592

template<bool F16OUT, bool BIAS, bool QSC>
__global__ void __launch_bounds__(256, 2)
tc_gemm(const __half* __restrict__ aHi,
        const __half* __restrict__ bHi,
        const float* __restrict__ bias,
        float* __restrict__ cF,
        __half* __restrict__ cH,
        int K, int lda, int ldb, int ldc,
        long aOut, long aIn, long bOut, long bIn, long cOut, long cIn,
        int Hdiv, float alpha)
{
    extern __shared__ __align__(128) char smem[];
    const uint32_t sb = smem_u32(smem);
    const int tid  = threadIdx.x;
    const int wid  = tid >> 5, lane = tid & 31;

    const int z  = blockIdx.z;
    const int zb = z / Hdiv, zh = z % Hdiv;
    const size_t aoff = (size_t)zb * aOut + (size_t)zh * aIn + (size_t)blockIdx.y * 128 * lda;
    const size_t boff = (size_t)zb * bOut + (size_t)zh * bIn + (size_t)blockIdx.x * 128 * ldb;
    aHi += aoff; bHi += boff;

    const int l_piece = tid & 7;        // 16B piece within 128B row
    const int l_rbase = tid >> 3;       // row base; +32 per rep

    #define LOAD_STAGE(kt, slot)                                                  \
    do {                                                                          \
        const uint32_t s_ = sb + (slot) * STAGE_G;                                \
        const int kb_ = (kt) * 64;                                                \
        _Pragma("unroll")                                                         \
        for (int i_ = 0; i_ < 4; i_++) {                                          \
            const int row_ = l_rbase + i_ * 32;                                   \
            cp16(s_ + row_*ROWB_G + l_piece*16,                                   \
                 aHi + (size_t)row_*lda + kb_ + l_piece*8);                       \
            cp16(s_ + MAT_G + row_*ROWB_G + l_piece*16,                           \
                 bHi + (size_t)row_*ldb + kb_ + l_piece*8);                       \
        }                                                                         \
    } while (0)

    const int wm = (wid >> 2) * 64;
    const int wn = (wid & 3) * 32;

    const int sel    = lane >> 3;
    const int within = lane & 7;
    const uint32_t aBase = (uint32_t)((wm + within + (sel & 1) * 8) * ROWB_G + (sel >> 1) * 16);
    const uint32_t bBase = (uint32_t)(MAT_G + (wn + within + (sel >> 1) * 8) * ROWB_G + (sel & 1) * 16);

    float acc[4][4][4];
    #pragma unroll
    for (int i = 0; i < 4; i++)
        #pragma unroll
        for (int j = 0; j < 4; j++)
            #pragma unroll
            for (int r = 0; r < 4; r++)
                acc[i][j][r] = 0.f;

    const int nk = K >> 6;

    LOAD_STAGE(0, 0); CP_COMMIT();
    if (nk > 1) LOAD_STAGE(1, 1);
    CP_COMMIT();
    CP_WAIT1();
    __syncthreads();

    for (int kt = 0; kt < nk; ++kt) {
        const uint32_t sS = sb + (kt % 3) * STAGE_G;
        #pragma unroll
        for (int ks = 0; ks < 4; ks++) {
            uint32_t aH[4][4], bH[4][2];
            #pragma unroll
            for (int mt = 0; mt < 4; mt++) {
                uint32_t ad = sS + aBase + mt * (16 * ROWB_G) + ks * 32;
                ldsm_x4(ad, aH[mt][0], aH[mt][1], aH[mt][2], aH[mt][3]);
            }
            #pragma unroll
            for (int p = 0; p < 2; p++) {
                uint32_t bd = sS + bBase + p * (16 * ROWB_G) + ks * 32;
                ldsm_x4(bd, bH[2*p][0], bH[2*p][1], bH[2*p+1][0], bH[2*p+1][1]);
            }
            #pragma unroll
            for (int mt = 0; mt < 4; mt++)
                #pragma unroll
                for (int nt = 0; nt < 4; nt++)
                    mma_f16(acc[mt][nt], aH[mt], bH[nt]);
        }
        // slot (kt+2)%3 was fully consumed at iteration kt-1 -> safe now.
        if (kt + 2 < nk) LOAD_STAGE(kt + 2, (kt + 2) % 3);
        CP_COMMIT();
        CP_WAIT1();        // stage kt+1 resident
        __syncthreads();
    }

    const size_t coff = (size_t)zb * cOut + (size_t)zh * cIn;
    const int gr = blockIdx.y * 128 + wm + (lane >> 2);
    const int gc = blockIdx.x * 128 + wn + (lane & 3) * 2;
    const float ts = (QSC && (blockIdx.x % 3 == 0)) ? QS2 : 1.0f;

    #pragma unroll
    for (int mt = 0; mt < 4; mt++) {
        #pragma unroll
        for (int nt = 0; nt < 4; nt++) {
            const int col = gc + nt * 8;
            float b0 = 0.f, b1 = 0.f;
            if (BIAS) { b0 = bias[col]; b1 = bias[col + 1]; }
            #pragma unroll
            for (int half_ = 0; half_ < 2; half_++) {
                const int row = gr + mt * 16 + half_ * 8;
                float v0 = (acc[mt][nt][half_ * 2]     * alpha + b0) * ts;
                float v1 = (acc[mt][nt][half_ * 2 + 1] * alpha + b1) * ts;
                if (F16OUT) {
                    *(uint32_t*)(cH + coff + (size_t)row * ldc + col) = trunc2h(v0, v1);
                } else {
                    float2 v; v.x = v0; v.y = v1;
                    *(float2*)(cF + coff + (size_t)row * ldc + col) = v;
                }
            }
        }
    }
    #undef LOAD_STAGE
}

// ---------------------------------------------------------------------------
// Flash attention (pure fp16), 2 CTAs/SM: per CTA = (head z, 64 q-rows),
// 128 threads = 4 warps x 16 rows. Q is pre-scaled by alpha*log2(e) so the
// softmax uses bare exp2f. SMEM: Q (4 d-chunks of 64 rows) + 4-slot PAIR ring
// (prefetch depth 2 -> cp.async.wait_group 2).
// ---------------------------------------------------------------------------
constexpr int ROWB    = 80;
constexpr int MAT_B   = 128 * ROWB;                // 10240: one 128x32 K/V chunk
constexpr int CHQ_B   = 64 * ROWB;                 // 5120:  one 64x32 Q chunk
constexpr int PAIR_B  = 2 * MAT_B;                 // 20480
constexpr int FQ_SZ   = 4 * CHQ_B;                 // 20480
constexpr int FSMEM   = FQ_SZ + 4 * PAIR_B;        // 102400 -> 2 CTAs/SM

// pair g: kt = g>>2, pr = g&3.  pr 0-1: K halves (d 0-63 / 64-127).
//                               pr 2-3: V key-chunk halves.  slot = g%4.
__device__ __forceinline__ void flash_issue_pair(
    int g, uint32_t sbKV, int lr0, int lp0,
    const __half* kH, const __half* vH)
{
    const int kt = g >> 2, pr = g & 3;
    const uint32_t dst = sbKV + (g % 4) * PAIR_B;
    if (pr < 2) {
        #pragma unroll
        for (int half = 0; half < 2; half++) {
            const int colb = (2 * pr + half) * 32 + lp0 * 8;
            const uint32_t d0 = dst + half * MAT_B;
            #pragma unroll
            for (int i = 0; i < 4; i++) {
                const int r = lr0 + i * 32;
                cp16(d0 + r*ROWB + lp0*16, kH + (size_t)(kt * 128 + r) * QKVW + colb);
            }
        }
    } else {
        #pragma unroll
        for (int half = 0; half < 2; half++) {
            const int colb = kt * 128 + (2 * (pr - 2) + half) * 32 + lp0 * 8;
            const uint32_t d0 = dst + half * MAT_B;
            #pragma unroll
            for (int i = 0; i < 4; i++) {
                const int r = lr0 + i * 32;
                cp16(d0 + r*ROWB + lp0*16, vH + (size_t)r * SEQ + colb);
            }
        }
    }
}

__global__ void __launch_bounds__(128, 2)
flash_kernel(const __half* __restrict__ qkH,
             const __half* __restrict__ vtH,
             __half* __restrict__ oH)
{
    extern __shared__ __align__(128) char smem[];
    const uint32_t sb = smem_u32(smem);
    const int tid  = threadIdx.x;
    const int wid  = tid >> 5, lane = tid & 31;
    const int qt   = blockIdx.x;
    const int z    = blockIdx.y;
    const int b    = z >> 4, h = z & 15;

    const __half* qH = qkH + (size_t)b * SEQ * QKVW + h * 384;
    const __half* kH = qH + 128;
    const __half* vH = vtH + (size_t)z * HD * SEQ;

    const int lr0 = tid >> 2;      // 0..31
    const int lp0 = tid & 3;

    const int q0 = qt * 64;
    // ---- load Q (4 d-chunks of 64 rows) ----
    #pragma unroll
    for (int c = 0; c < 4; c++) {
        const uint32_t d0 = sb + c * CHQ_B;
        const int colb = c * 32 + lp0 * 8;
        #pragma unroll
        for (int i = 0; i < 2; i++) {
            const int r = lr0 + i * 32;
            cp16(d0 + r*ROWB + lp0*16, qH + (size_t)(q0 + r) * QKVW + colb);
        }
    }
    CP_COMMIT();
    flash_issue_pair(0, sb + FQ_SZ, lr0, lp0, kH, vH); CP_COMMIT();
    flash_issue_pair(1, sb + FQ_SZ, lr0, lp0, kH, vH); CP_COMMIT();
    flash_issue_pair(2, sb + FQ_SZ, lr0, lp0, kH, vH); CP_COMMIT();

    const int sel    = lane >> 3;
    const int within = lane & 7;
    const uint32_t aOff  = (uint32_t)((wid * 16 + within + (sel & 1) * 8) * ROWB + (sel >> 1) * 16);
    const uint32_t bOffB = (uint32_t)((within + (sel >> 1) * 8) * ROWB + (sel & 1) * 16);

    float o[16][4];
    #pragma unroll
    for (int i = 0; i < 16; i++)
        #pragma unroll
        for (int j = 0; j < 4; j++) o[i][j] = 0.f;
    float s[16][4];
    uint32_t pfH[8][4];
    float mA = -1e30f, mB = -1e30f, lA = 0.f, lB = 0.f;

    for (int kt = 0; kt < 16; ++kt) {
        #pragma unroll
        for (int pr = 0; pr < 4; ++pr) {
            const int g = kt * 4 + pr;
            if (g + 2 < 64)      { CP_WAIT2(); }
            else if (g + 1 < 64) { CP_WAIT1(); }
            else                 { CP_WAIT0(); }
            __syncthreads();
            // slot (g+3)%4 was consumed at pair g-1, fenced by the sync above.
            if (g + 3 < 64) {
                flash_issue_pair(g + 3, sb + FQ_SZ, lr0, lp0, kH, vH);
                CP_COMMIT();
            }
            const uint32_t slotB = sb + FQ_SZ + (g % 4) * PAIR_B;

            if (pr < 2) {
                // ---- S-phase: d-chunks 2*pr, 2*pr+1 ----
                if (pr == 0) {
                    #pragma unroll
                    for (int i = 0; i < 16; i++)
                        #pragma unroll
                        for (int j = 0; j < 4; j++) s[i][j] = 0.f;
                }
                #pragma unroll
                for (int half = 0; half < 2; half++) {
                    const uint32_t qc  = sb + (2 * pr + half) * CHQ_B;
                    const uint32_t kvc = slotB + half * MAT_B;
                    #pragma unroll
                    for (int ks = 0; ks < 2; ks++) {
                        uint32_t aH4[4];
                        ldsm_x4(qc + aOff + ks*32, aH4[0], aH4[1], aH4[2], aH4[3]);
                        #pragma unroll
                        for (int p = 0; p < 8; p++) {
                            uint32_t bh[4];
                            ldsm_x4(kvc + bOffB + p*(16*ROWB) + ks*32,
                                    bh[0], bh[1], bh[2], bh[3]);
                            mma_f16(s[2*p],   aH4, bh);
                            mma_f16(s[2*p+1], aH4, bh + 2);
                        }
                    }
                }
            } else {
                if (pr == 2) {
                    // ---- online softmax (log2 domain; Q pre-scaled) ----
                    float mtA = -1e30f, mtB = -1e30f;
                    #pragma unroll
                    for (int nt = 0; nt < 16; nt++) {
                        mtA = fmaxf(mtA, fmaxf(s[nt][0], s[nt][1]));
                        mtB = fmaxf(mtB, fmaxf(s[nt][2], s[nt][3]));
                    }
                    mtA = fmaxf(mtA, __shfl_xor_sync(~0u, mtA, 1));
                    mtA = fmaxf(mtA, __shfl_xor_sync(~0u, mtA, 2));
                    mtB = fmaxf(mtB, __shfl_xor_sync(~0u, mtB, 1));
                    mtB = fmaxf(mtB, __shfl_xor_sync(~0u, mtB, 2));
                    const float mnA = fmaxf(mA, mtA);
                    const float mnB = fmaxf(mB, mtB);
                    const float fA = exp2f(mA - mnA);
                    const float fB = exp2f(mB - mnB);
                    #pragma unroll
                    for (int nt = 0; nt < 16; nt++) {
                        o[nt][0] *= fA; o[nt][1] *= fA;
                        o[nt][2] *= fB; o[nt][3] *= fB;
                    }
                    float sA = 0.f, sB = 0.f;
                    #pragma unroll
                    for (int nt = 0; nt < 16; nt++) {
                        const float p0 = exp2f(s[nt][0] - mnA);
                        const float p1 = exp2f(s[nt][1] - mnA);
                        const float p2 = exp2f(s[nt][2] - mnB);
                        const float p3 = exp2f(s[nt][3] - mnB);
                        sA += p0 + p1; sB += p2 + p3;
                        const uint32_t h01 = trunc2h(p0, p1);
                        const uint32_t h23 = trunc2h(p2, p3);
                        const int kf = nt >> 1;
                        if ((nt & 1) == 0) {
                            pfH[kf][0] = h01; pfH[kf][1] = h23;
                        } else {
                            pfH[kf][2] = h01; pfH[kf][3] = h23;
                        }
                    }
                    sA += __shfl_xor_sync(~0u, sA, 1);
                    sA += __shfl_xor_sync(~0u, sA, 2);
                    sB += __shfl_xor_sync(~0u, sB, 1);
                    sB += __shfl_xor_sync(~0u, sB, 2);
                    lA = lA * fA + sA;
                    lB = lB * fB + sB;
                    mA = mnA; mB = mnB;
                }
                // ---- PV-phase: V key-chunks 2*(pr-2), 2*(pr-2)+1 ----
                #pragma unroll
                for (int half = 0; half < 2; half++) {
                    const int c = 2 * (pr - 2) + half;
                    const uint32_t kvc = slotB + half * MAT_B;
                    #pragma unroll
                    for (int ks = 0; ks < 2; ks++) {
                        const int kf = 2 * c + ks;
                        #pragma unroll
                        for (int p = 0; p < 8; p++) {
                            uint32_t bh[4];
                            ldsm_x4(kvc + bOffB + p*(16*ROWB) + ks*32,
                                    bh[0], bh[1], bh[2], bh[3]);
                            mma_f16(o[2*p],   pfH[kf], bh);
                            mma_f16(o[2*p+1], pfH[kf], bh + 2);
                        }
                    }
                }
            }
        }
    }

    const float invA = 1.f / lA;
    const float invB = 1.f / lB;
    const size_t rowA = (size_t)b * SEQ + q0 + wid * 16 + (lane >> 2);
    const size_t baseA = rowA * DMODEL + h * 128 + (lane & 3) * 2;
    const size_t baseB = baseA + (size_t)8 * DMODEL;
    #pragma unroll
    for (int nt = 0; nt < 16; nt++) {
        *(uint32_t*)(oH + baseA + nt * 8) = trunc2h(o[nt][0] * invA, o[nt][1] * invA);
        *(uint32_t*)(oH + baseB + nt * 8) = trunc2h(o[nt][2] * invB, o[nt][3] * invB);
    }
}

// ---------------------------------------------------------------------------
// fp32 -> fp16 truncate (elementwise, float4)
// ---------------------------------------------------------------------------
__global__ void __launch_bounds__(256)
trunc_kernel(const float* __restrict__ in, __half* __restrict__ hi)
{
    const long i = (long)blockIdx.x * 256 + threadIdx.x;
    float4 v = ((const float4*)in)[i];
    ((uint32_t*)hi)[i * 2]     = trunc2h(v.x, v.y);
    ((uint32_t*)hi)[i * 2 + 1] = trunc2h(v.z, v.w);
}

// ---------------------------------------------------------------------------
// V transpose: qkv (v slice) -> Vt [z=bh][d][s]
// ---------------------------------------------------------------------------
__global__ void __launch_bounds__(256)
transpose_v(const __half* __restrict__ qH, __half* __restrict__ vH)
{
    __shared__ __half tH[32][33];
    const int z = blockIdx.z, b = z >> 4, h = z & 15;
    const int s0 = blockIdx.x * 32, d0 = blockIdx.y * 32;
    const int tx = threadIdx.x & 31, ty = threadIdx.x >> 5;
    const size_t ibase = (size_t)b * SEQ * QKVW + (size_t)h * 384 + 256;
    #pragma unroll
    for (int i = 0; i < 4; i++) {
        int s = s0 + ty + i * 8;
        tH[ty + i * 8][tx] = qH[ibase + (size_t)s * QKVW + d0 + tx];
    }
    __syncthreads();
    const size_t obase = (size_t)z * HD * SEQ;
    #pragma unroll
    for (int i = 0; i < 4; i++) {
        int d = d0 + ty + i * 8;
        vH[obase + (size_t)d * SEQ + s0 + tx] = tH[tx][ty + i * 8];
    }
}

// ---------------------------------------------------------------------------
extern "C" void kernel_launch(void* const* d_in, const int* in_sizes, int n_in,
                              void* d_out, int out_size)
{
    const float* x     = (const float*)d_in[0];
    const float* w_qkv = (const float*)d_in[2];
    const float* b_qkv = (const float*)d_in[3];
    const float* w_o   = (const float*)d_in[4];
    const float* b_o   = (const float*)d_in[5];
    float* out = (float*)d_out;

    __half *xsH, *wqH, *woH, *qkH, *vtH, *atH;
    cudaGetSymbolAddress((void**)&xsH, g_xsHi);
    cudaGetSymbolAddress((void**)&wqH, g_wqHi);
    cudaGetSymbolAddress((void**)&woH, g_woHi);
    cudaGetSymbolAddress((void**)&qkH, g_qkvHi);
    cudaGetSymbolAddress((void**)&vtH, g_vtHi);
    cudaGetSymbolAddress((void**)&atH, g_atHi);

    cudaFuncSetAttribute(tc_gemm<true,  true, true >, cudaFuncAttributeMaxDynamicSharedMemorySize, SMEM_G);
    cudaFuncSetAttribute(tc_gemm<false, true, false>, cudaFuncAttributeMaxDynamicSharedMemorySize, SMEM_G);
    cudaFuncSetAttribute(flash_kernel, cudaFuncAttributeMaxDynamicSharedMemorySize, FSMEM);

    // 0) truncate inputs to fp16
    trunc_kernel<<<(long)BATCH*SEQ*DMODEL/1024, 256>>>(x,     xsH);
    trunc_kernel<<<(long)QKVW*DMODEL/1024,      256>>>(w_qkv, wqH);
    trunc_kernel<<<(long)DMODEL*DMODEL/1024,    256>>>(w_o,   woH);

    // 1) QKV projection -> qkv fp16 (bias fused; q-tiles pre-scaled by QS2)
    {
        dim3 grid(QKVW / 128, (BATCH * SEQ) / 128, 1);
        tc_gemm<true, true, true><<<grid, 256, SMEM_G>>>(
            xsH, wqH, b_qkv, nullptr, qkH,
            DMODEL, DMODEL, DMODEL, QKVW,
            0, 0, 0, 0, 0, 0, 1, 1.0f);
    }

    // 2) V transpose -> Vt fp16
    transpose_v<<<dim3(SEQ / 32, HD / 32, BH), 256>>>(qkH, vtH);

    // 3) fused flash attention -> attn fp16  (64 q-rows per CTA, 2 CTAs/SM)
    flash_kernel<<<dim3(SEQ / 64, BH), 128, FSMEM>>>(qkH, vtH, atH);

    // 4) output projection (bias fused) -> out fp32
    {
        dim3 grid(DMODEL / 128, (BATCH * SEQ) / 128, 1);
        tc_gemm<false, true, false><<<grid, 256, SMEM_G>>>(
            atH, woH, b_o, out, nullptr,
            DMODEL, DMODEL, DMODEL, DMODEL,
            0, 0, 0, 0, 0, 0, 1, 1.0f);
    }
}

// round 15
// speedup vs baseline: 1.0224x; 1.0224x over previous
#include <cuda_runtime.h>
#include <cuda_fp16.h>
#include <cstdint>

// Problem shape (fixed): B=2, S=2048, D=2048, H=16, DK=128
constexpr int BATCH  = 2;
constexpr int SEQ    = 2048;
constexpr int DMODEL = 2048;
constexpr int NH     = 16;
constexpr int HD     = 128;
constexpr int QKVW   = 3 * DMODEL;   // 6144
constexpr int BH     = BATCH * NH;   // 32

// q pre-scale: 1/sqrt(128) * log2(e)  (folded so softmax uses bare exp2)
constexpr float QS2 = 0.08838834764831845f * 1.4426950408889634f;

// ---------------------------------------------------------------------------
// Scratch (device globals — allocation-free per harness rules)
// ---------------------------------------------------------------------------
__device__ __half g_xsHi [(long)BATCH * SEQ * DMODEL];
__device__ __half g_wqHi [(long)QKVW * DMODEL];
__device__ __half g_woHi [(long)DMODEL * DMODEL];
__device__ __half g_qkvHi[(long)BATCH * SEQ * QKVW];
__device__ __half g_vtHi [(long)BH * HD * SEQ];
__device__ __half g_atHi [(long)BATCH * SEQ * DMODEL];

// ---------------------------------------------------------------------------
// helpers
// ---------------------------------------------------------------------------
__device__ __forceinline__ uint32_t smem_u32(const void* p) {
    uint32_t a;
    asm("{ .reg .u64 t; cvta.to.shared.u64 t, %1; cvt.u32.u64 %0, t; }"
        : "=r"(a) : "l"(p));
    return a;
}
__device__ __forceinline__ void cp16(uint32_t saddr, const void* g) {
    asm volatile("cp.async.cg.shared.global [%0], [%1], 16;" :: "r"(saddr), "l"(g));
}
#define CP_COMMIT() asm volatile("cp.async.commit_group;" ::: "memory")
#define CP_WAIT1()  asm volatile("cp.async.wait_group 1;" ::: "memory")
#define CP_WAIT0()  asm volatile("cp.async.wait_group 0;" ::: "memory")

__device__ __forceinline__ void ldsm_x4(uint32_t addr, uint32_t& r0, uint32_t& r1,
                                        uint32_t& r2, uint32_t& r3) {
    asm volatile("ldmatrix.sync.aligned.m8n8.x4.shared.b16 {%0,%1,%2,%3}, [%4];"
                 : "=r"(r0), "=r"(r1), "=r"(r2), "=r"(r3) : "r"(addr));
}
__device__ __forceinline__ void mma_f16(float* c, const uint32_t* a, const uint32_t* b) {
    asm volatile(
        "mma.sync.aligned.m16n8k16.row.col.f32.f16.f16.f32 "
        "{%0,%1,%2,%3}, {%4,%5,%6,%7}, {%8,%9}, {%0,%1,%2,%3};"
        : "+f"(c[0]), "+f"(c[1]), "+f"(c[2]), "+f"(c[3])
        : "r"(a[0]), "r"(a[1]), "r"(a[2]), "r"(a[3]), "r"(b[0]), "r"(b[1]));
}
__device__ __forceinline__ uint32_t trunc2h(float v0, float v1) {
    __half2 t = __floats2half2_rn(v0, v1);   // single F2FP.PACK instruction
    return *(uint32_t*)&t;
}

// ---------------------------------------------------------------------------
// HMMA GEMM (pure fp16): C[m,n] = sum_k Ah[m,k] * Bh[n,k]  (NT)
// CTA tile 128x128, BK=64, 3-stage cp.async (1 sync/iter, prefetch at bottom).
// 8 warps (2x4), warp tile 64x32. 144B padded rows. 2 CTAs/SM.
// QSC: multiply q-tiles (blockIdx.x%3==0) by QS2 after bias (exp2 folding).
// ---------------------------------------------------------------------------
constexpr int ROWB_G  = 144;              // 64 fp16 = 128B data + 16B pad
constexpr int MAT_G   = 128 * ROWB_G;     // 18432
constexpr int STAGE_G = 2 * MAT_G;        // Ah, Bh = 36864
constexpr int SMEM_G  = 3 * STAGE_G;      // 110592

template<bool F16OUT, bool BIAS, bool QSC>
__global__ void __launch_bounds__(256, 2)
tc_gemm(const __half* __restrict__ aHi,
        const __half* __restrict__ bHi,
        const float* __restrict__ bias,
        float* __restrict__ cF,
        __half* __restrict__ cH,
        int K, int lda, int ldb, int ldc,
        long aOut, long aIn, long bOut, long bIn, long cOut, long cIn,
        int Hdiv, float alpha)
{
    extern __shared__ __align__(128) char smem[];
    const uint32_t sb = smem_u32(smem);
    const int tid  = threadIdx.x;
    const int wid  = tid >> 5, lane = tid & 31;

    const int z  = blockIdx.z;
    const int zb = z / Hdiv, zh = z % Hdiv;
    const size_t aoff = (size_t)zb * aOut + (size_t)zh * aIn + (size_t)blockIdx.y * 128 * lda;
    const size_t boff = (size_t)zb * bOut + (size_t)zh * bIn + (size_t)blockIdx.x * 128 * ldb;
    aHi += aoff; bHi += boff;

    const int l_piece = tid & 7;        // 16B piece within 128B row
    const int l_rbase = tid >> 3;       // row base; +32 per rep

    #define LOAD_STAGE(kt, slot)                                                  \
    do {                                                                          \
        const uint32_t s_ = sb + (slot) * STAGE_G;                                \
        const int kb_ = (kt) * 64;                                                \
        _Pragma("unroll")                                                         \
        for (int i_ = 0; i_ < 4; i_++) {                                          \
            const int row_ = l_rbase + i_ * 32;                                   \
            cp16(s_ + row_*ROWB_G + l_piece*16,                                   \
                 aHi + (size_t)row_*lda + kb_ + l_piece*8);                       \
            cp16(s_ + MAT_G + row_*ROWB_G + l_piece*16,                           \
                 bHi + (size_t)row_*ldb + kb_ + l_piece*8);                       \
        }                                                                         \
    } while (0)

    const int wm = (wid >> 2) * 64;
    const int wn = (wid & 3) * 32;

    const int sel    = lane >> 3;
    const int within = lane & 7;
    const uint32_t aBase = (uint32_t)((wm + within + (sel & 1) * 8) * ROWB_G + (sel >> 1) * 16);
    const uint32_t bBase = (uint32_t)(MAT_G + (wn + within + (sel >> 1) * 8) * ROWB_G + (sel & 1) * 16);

    float acc[4][4][4];
    #pragma unroll
    for (int i = 0; i < 4; i++)
        #pragma unroll
        for (int j = 0; j < 4; j++)
            #pragma unroll
            for (int r = 0; r < 4; r++)
                acc[i][j][r] = 0.f;

    const int nk = K >> 6;

    LOAD_STAGE(0, 0); CP_COMMIT();
    if (nk > 1) LOAD_STAGE(1, 1);
    CP_COMMIT();
    CP_WAIT1();
    __syncthreads();

    for (int kt = 0; kt < nk; ++kt) {
        const uint32_t sS = sb + (kt % 3) * STAGE_G;
        #pragma unroll
        for (int ks = 0; ks < 4; ks++) {
            uint32_t aH[4][4], bH[4][2];
            #pragma unroll
            for (int mt = 0; mt < 4; mt++) {
                uint32_t ad = sS + aBase + mt * (16 * ROWB_G) + ks * 32;
                ldsm_x4(ad, aH[mt][0], aH[mt][1], aH[mt][2], aH[mt][3]);
            }
            #pragma unroll
            for (int p = 0; p < 2; p++) {
                uint32_t bd = sS + bBase + p * (16 * ROWB_G) + ks * 32;
                ldsm_x4(bd, bH[2*p][0], bH[2*p][1], bH[2*p+1][0], bH[2*p+1][1]);
            }
            #pragma unroll
            for (int mt = 0; mt < 4; mt++)
                #pragma unroll
                for (int nt = 0; nt < 4; nt++)
                    mma_f16(acc[mt][nt], aH[mt], bH[nt]);
        }
        // slot (kt+2)%3 was fully consumed at iteration kt-1 -> safe now.
        if (kt + 2 < nk) LOAD_STAGE(kt + 2, (kt + 2) % 3);
        CP_COMMIT();
        CP_WAIT1();        // stage kt+1 resident
        __syncthreads();
    }

    const size_t coff = (size_t)zb * cOut + (size_t)zh * cIn;
    const int gr = blockIdx.y * 128 + wm + (lane >> 2);
    const int gc = blockIdx.x * 128 + wn + (lane & 3) * 2;
    const float ts = (QSC && (blockIdx.x % 3 == 0)) ? QS2 : 1.0f;

    #pragma unroll
    for (int mt = 0; mt < 4; mt++) {
        #pragma unroll
        for (int nt = 0; nt < 4; nt++) {
            const int col = gc + nt * 8;
            float b0 = 0.f, b1 = 0.f;
            if (BIAS) { b0 = bias[col]; b1 = bias[col + 1]; }
            #pragma unroll
            for (int half_ = 0; half_ < 2; half_++) {
                const int row = gr + mt * 16 + half_ * 8;
                float v0 = (acc[mt][nt][half_ * 2]     * alpha + b0) * ts;
                float v1 = (acc[mt][nt][half_ * 2 + 1] * alpha + b1) * ts;
                if (F16OUT) {
                    *(uint32_t*)(cH + coff + (size_t)row * ldc + col) = trunc2h(v0, v1);
                } else {
                    float2 v; v.x = v0; v.y = v1;
                    *(float2*)(cF + coff + (size_t)row * ldc + col) = v;
                }
            }
        }
    }
    #undef LOAD_STAGE
}

// ---------------------------------------------------------------------------
// Flash attention (pure fp16), 2 CTAs/SM: per CTA = (head z, 64 q-rows),
// 128 threads = 4 warps x 16 rows. Q pre-scaled by alpha*log2(e) -> bare exp2.
// SMEM: Q (4 d-chunks of 64 rows) + 3-slot PAIR ring (R13 measured-best).
// ---------------------------------------------------------------------------
constexpr int ROWB    = 80;
constexpr int MAT_B   = 128 * ROWB;                // 10240: one 128x32 K/V chunk
constexpr int CHQ_B   = 64 * ROWB;                 // 5120:  one 64x32 Q chunk
constexpr int PAIR_B  = 2 * MAT_B;                 // 20480
constexpr int FQ_SZ   = 4 * CHQ_B;                 // 20480
constexpr int FSMEM   = FQ_SZ + 3 * PAIR_B;        // 81920 -> 2 CTAs/SM

// pair g: kt = g>>2, pr = g&3.  pr 0-1: K halves (d 0-63 / 64-127).
//                               pr 2-3: V key-chunk halves.  slot = g%3.
__device__ __forceinline__ void flash_issue_pair(
    int g, uint32_t sbKV, int lr0, int lp0,
    const __half* kH, const __half* vH)
{
    const int kt = g >> 2, pr = g & 3;
    const uint32_t dst = sbKV + (g % 3) * PAIR_B;
    if (pr < 2) {
        #pragma unroll
        for (int half = 0; half < 2; half++) {
            const int colb = (2 * pr + half) * 32 + lp0 * 8;
            const uint32_t d0 = dst + half * MAT_B;
            #pragma unroll
            for (int i = 0; i < 4; i++) {
                const int r = lr0 + i * 32;
                cp16(d0 + r*ROWB + lp0*16, kH + (size_t)(kt * 128 + r) * QKVW + colb);
            }
        }
    } else {
        #pragma unroll
        for (int half = 0; half < 2; half++) {
            const int colb = kt * 128 + (2 * (pr - 2) + half) * 32 + lp0 * 8;
            const uint32_t d0 = dst + half * MAT_B;
            #pragma unroll
            for (int i = 0; i < 4; i++) {
                const int r = lr0 + i * 32;
                cp16(d0 + r*ROWB + lp0*16, vH + (size_t)r * SEQ + colb);
            }
        }
    }
}

__global__ void __launch_bounds__(128, 2)
flash_kernel(const __half* __restrict__ qkH,
             const __half* __restrict__ vtH,
             __half* __restrict__ oH)
{
    extern __shared__ __align__(128) char smem[];
    const uint32_t sb = smem_u32(smem);
    const int tid  = threadIdx.x;
    const int wid  = tid >> 5, lane = tid & 31;
    const int qt   = blockIdx.x;
    const int z    = blockIdx.y;
    const int b    = z >> 4, h = z & 15;

    const __half* qH = qkH + (size_t)b * SEQ * QKVW + h * 384;
    const __half* kH = qH + 128;
    const __half* vH = vtH + (size_t)z * HD * SEQ;

    const int lr0 = tid >> 2;      // 0..31
    const int lp0 = tid & 3;

    const int q0 = qt * 64;
    // ---- load Q (4 d-chunks of 64 rows) ----
    #pragma unroll
    for (int c = 0; c < 4; c++) {
        const uint32_t d0 = sb + c * CHQ_B;
        const int colb = c * 32 + lp0 * 8;
        #pragma unroll
        for (int i = 0; i < 2; i++) {
            const int r = lr0 + i * 32;
            cp16(d0 + r*ROWB + lp0*16, qH + (size_t)(q0 + r) * QKVW + colb);
        }
    }
    CP_COMMIT();
    flash_issue_pair(0, sb + FQ_SZ, lr0, lp0, kH, vH); CP_COMMIT();
    flash_issue_pair(1, sb + FQ_SZ, lr0, lp0, kH, vH); CP_COMMIT();

    const int sel    = lane >> 3;
    const int within = lane & 7;
    const uint32_t aOff  = (uint32_t)((wid * 16 + within + (sel & 1) * 8) * ROWB + (sel >> 1) * 16);
    const uint32_t bOffB = (uint32_t)((within + (sel >> 1) * 8) * ROWB + (sel & 1) * 16);

    float o[16][4];
    #pragma unroll
    for (int i = 0; i < 16; i++)
        #pragma unroll
        for (int j = 0; j < 4; j++) o[i][j] = 0.f;
    float s[16][4];
    uint32_t pfH[8][4];
    float mA = -1e30f, mB = -1e30f, lA = 0.f, lB = 0.f;

    for (int kt = 0; kt < 16; ++kt) {
        #pragma unroll
        for (int pr = 0; pr < 4; ++pr) {
            const int g = kt * 4 + pr;
            if (g + 1 < 64) { CP_WAIT1(); } else { CP_WAIT0(); }
            __syncthreads();
            if (g + 2 < 64) {
                flash_issue_pair(g + 2, sb + FQ_SZ, lr0, lp0, kH, vH);
                CP_COMMIT();
            }
            const uint32_t slotB = sb + FQ_SZ + (g % 3) * PAIR_B;

            if (pr < 2) {
                // ---- S-phase: d-chunks 2*pr, 2*pr+1 ----
                if (pr == 0) {
                    #pragma unroll
                    for (int i = 0; i < 16; i++)
                        #pragma unroll
                        for (int j = 0; j < 4; j++) s[i][j] = 0.f;
                }
                #pragma unroll
                for (int half = 0; half < 2; half++) {
                    const uint32_t qc  = sb + (2 * pr + half) * CHQ_B;
                    const uint32_t kvc = slotB + half * MAT_B;
                    #pragma unroll
                    for (int ks = 0; ks < 2; ks++) {
                        uint32_t aH4[4];
                        ldsm_x4(qc + aOff + ks*32, aH4[0], aH4[1], aH4[2], aH4[3]);
                        #pragma unroll
                        for (int p = 0; p < 8; p++) {
                            uint32_t bh[4];
                            ldsm_x4(kvc + bOffB + p*(16*ROWB) + ks*32,
                                    bh[0], bh[1], bh[2], bh[3]);
                            mma_f16(s[2*p],   aH4, bh);
                            mma_f16(s[2*p+1], aH4, bh + 2);
                        }
                    }
                }
            } else {
                if (pr == 2) {
                    // ---- online softmax (log2 domain; Q pre-scaled) ----
                    float mtA = -1e30f, mtB = -1e30f;
                    #pragma unroll
                    for (int nt = 0; nt < 16; nt++) {
                        mtA = fmaxf(mtA, fmaxf(s[nt][0], s[nt][1]));
                        mtB = fmaxf(mtB, fmaxf(s[nt][2], s[nt][3]));
                    }
                    mtA = fmaxf(mtA, __shfl_xor_sync(~0u, mtA, 1));
                    mtA = fmaxf(mtA, __shfl_xor_sync(~0u, mtA, 2));
                    mtB = fmaxf(mtB, __shfl_xor_sync(~0u, mtB, 1));
                    mtB = fmaxf(mtB, __shfl_xor_sync(~0u, mtB, 2));
                    const float mnA = fmaxf(mA, mtA);
                    const float mnB = fmaxf(mB, mtB);
                    const float fA = exp2f(mA - mnA);
                    const float fB = exp2f(mB - mnB);
                    #pragma unroll
                    for (int nt = 0; nt < 16; nt++) {
                        o[nt][0] *= fA; o[nt][1] *= fA;
                        o[nt][2] *= fB; o[nt][3] *= fB;
                    }
                    float sA = 0.f, sB = 0.f;
                    #pragma unroll
                    for (int nt = 0; nt < 16; nt++) {
                        const float p0 = exp2f(s[nt][0] - mnA);
                        const float p1 = exp2f(s[nt][1] - mnA);
                        const float p2 = exp2f(s[nt][2] - mnB);
                        const float p3 = exp2f(s[nt][3] - mnB);
                        sA += p0 + p1; sB += p2 + p3;
                        const uint32_t h01 = trunc2h(p0, p1);
                        const uint32_t h23 = trunc2h(p2, p3);
                        const int kf = nt >> 1;
                        if ((nt & 1) == 0) {
                            pfH[kf][0] = h01; pfH[kf][1] = h23;
                        } else {
                            pfH[kf][2] = h01; pfH[kf][3] = h23;
                        }
                    }
                    sA += __shfl_xor_sync(~0u, sA, 1);
                    sA += __shfl_xor_sync(~0u, sA, 2);
                    sB += __shfl_xor_sync(~0u, sB, 1);
                    sB += __shfl_xor_sync(~0u, sB, 2);
                    lA = lA * fA + sA;
                    lB = lB * fB + sB;
                    mA = mnA; mB = mnB;
                }
                // ---- PV-phase: V key-chunks 2*(pr-2), 2*(pr-2)+1 ----
                #pragma unroll
                for (int half = 0; half < 2; half++) {
                    const int c = 2 * (pr - 2) + half;
                    const uint32_t kvc = slotB + half * MAT_B;
                    #pragma unroll
                    for (int ks = 0; ks < 2; ks++) {
                        const int kf = 2 * c + ks;
                        #pragma unroll
                        for (int p = 0; p < 8; p++) {
                            uint32_t bh[4];
                            ldsm_x4(kvc + bOffB + p*(16*ROWB) + ks*32,
                                    bh[0], bh[1], bh[2], bh[3]);
                            mma_f16(o[2*p],   pfH[kf], bh);
                            mma_f16(o[2*p+1], pfH[kf], bh + 2);
                        }
                    }
                }
            }
        }
    }

    const float invA = 1.f / lA;
    const float invB = 1.f / lB;
    const size_t rowA = (size_t)b * SEQ + q0 + wid * 16 + (lane >> 2);
    const size_t baseA = rowA * DMODEL + h * 128 + (lane & 3) * 2;
    const size_t baseB = baseA + (size_t)8 * DMODEL;
    #pragma unroll
    for (int nt = 0; nt < 16; nt++) {
        *(uint32_t*)(oH + baseA + nt * 8) = trunc2h(o[nt][0] * invA, o[nt][1] * invA);
        *(uint32_t*)(oH + baseB + nt * 8) = trunc2h(o[nt][2] * invB, o[nt][3] * invB);
    }
}

// ---------------------------------------------------------------------------
// fp32 -> fp16 truncate (elementwise, float4)
// ---------------------------------------------------------------------------
__global__ void __launch_bounds__(256)
trunc_kernel(const float* __restrict__ in, __half* __restrict__ hi)
{
    const long i = (long)blockIdx.x * 256 + threadIdx.x;
    float4 v = ((const float4*)in)[i];
    ((uint32_t*)hi)[i * 2]     = trunc2h(v.x, v.y);
    ((uint32_t*)hi)[i * 2 + 1] = trunc2h(v.z, v.w);
}

// ---------------------------------------------------------------------------
// V transpose: qkv (v slice) -> Vt [z=bh][d][s]
// ---------------------------------------------------------------------------
__global__ void __launch_bounds__(256)
transpose_v(const __half* __restrict__ qH, __half* __restrict__ vH)
{
    __shared__ __half tH[32][33];
    const int z = blockIdx.z, b = z >> 4, h = z & 15;
    const int s0 = blockIdx.x * 32, d0 = blockIdx.y * 32;
    const int tx = threadIdx.x & 31, ty = threadIdx.x >> 5;
    const size_t ibase = (size_t)b * SEQ * QKVW + (size_t)h * 384 + 256;
    #pragma unroll
    for (int i = 0; i < 4; i++) {
        int s = s0 + ty + i * 8;
        tH[ty + i * 8][tx] = qH[ibase + (size_t)s * QKVW + d0 + tx];
    }
    __syncthreads();
    const size_t obase = (size_t)z * HD * SEQ;
    #pragma unroll
    for (int i = 0; i < 4; i++) {
        int d = d0 + ty + i * 8;
        vH[obase + (size_t)d * SEQ + s0 + tx] = tH[tx][ty + i * 8];
    }
}

// ---------------------------------------------------------------------------
extern "C" void kernel_launch(void* const* d_in, const int* in_sizes, int n_in,
                              void* d_out, int out_size)
{
    const float* x     = (const float*)d_in[0];
    const float* w_qkv = (const float*)d_in[2];
    const float* b_qkv = (const float*)d_in[3];
    const float* w_o   = (const float*)d_in[4];
    const float* b_o   = (const float*)d_in[5];
    float* out = (float*)d_out;

    __half *xsH, *wqH, *woH, *qkH, *vtH, *atH;
    cudaGetSymbolAddress((void**)&xsH, g_xsHi);
    cudaGetSymbolAddress((void**)&wqH, g_wqHi);
    cudaGetSymbolAddress((void**)&woH, g_woHi);
    cudaGetSymbolAddress((void**)&qkH, g_qkvHi);
    cudaGetSymbolAddress((void**)&vtH, g_vtHi);
    cudaGetSymbolAddress((void**)&atH, g_atHi);

    cudaFuncSetAttribute(tc_gemm<true,  true, true >, cudaFuncAttributeMaxDynamicSharedMemorySize, SMEM_G);
    cudaFuncSetAttribute(tc_gemm<false, true, false>, cudaFuncAttributeMaxDynamicSharedMemorySize, SMEM_G);
    cudaFuncSetAttribute(flash_kernel, cudaFuncAttributeMaxDynamicSharedMemorySize, FSMEM);

    // 0) truncate inputs to fp16
    trunc_kernel<<<(long)BATCH*SEQ*DMODEL/1024, 256>>>(x,     xsH);
    trunc_kernel<<<(long)QKVW*DMODEL/1024,      256>>>(w_qkv, wqH);
    trunc_kernel<<<(long)DMODEL*DMODEL/1024,    256>>>(w_o,   woH);

    // 1) QKV projection -> qkv fp16 (bias fused; q-tiles pre-scaled by QS2)
    {
        dim3 grid(QKVW / 128, (BATCH * SEQ) / 128, 1);
        tc_gemm<true, true, true><<<grid, 256, SMEM_G>>>(
            xsH, wqH, b_qkv, nullptr, qkH,
            DMODEL, DMODEL, DMODEL, QKVW,
            0, 0, 0, 0, 0, 0, 1, 1.0f);
    }

    // 2) V transpose -> Vt fp16
    transpose_v<<<dim3(SEQ / 32, HD / 32, BH), 256>>>(qkH, vtH);

    // 3) fused flash attention -> attn fp16  (64 q-rows per CTA, 2 CTAs/SM)
    flash_kernel<<<dim3(SEQ / 64, BH), 128, FSMEM>>>(qkH, vtH, atH);

    // 4) output projection (bias fused) -> out fp32
    {
        dim3 grid(DMODEL / 128, (BATCH * SEQ) / 128, 1);
        tc_gemm<false, true, false><<<grid, 256, SMEM_G>>>(
            atH, woH, b_o, out, nullptr,
            DMODEL, DMODEL, DMODEL, DMODEL,
            0, 0, 0, 0, 0, 0, 1, 1.0f);
    }
}

// round 16
// speedup vs baseline: 1.0316x; 1.0090x over previous
#include <cuda_runtime.h>
#include <cuda_fp16.h>
#include <cstdint>

// Problem shape (fixed): B=2, S=2048, D=2048, H=16, DK=128
constexpr int BATCH  = 2;
constexpr int SEQ    = 2048;
constexpr int DMODEL = 2048;
constexpr int NH     = 16;
constexpr int HD     = 128;
constexpr int QKVW   = 3 * DMODEL;   // 6144
constexpr int BH     = BATCH * NH;   // 32

// q pre-scale: 1/sqrt(128) * log2(e)  (folded so softmax uses bare exp2)
constexpr float QS2 = 0.08838834764831845f * 1.4426950408889634f;

// ---------------------------------------------------------------------------
// Scratch (device globals — allocation-free per harness rules)
// ---------------------------------------------------------------------------
__device__ __half g_xsHi [(long)BATCH * SEQ * DMODEL];
__device__ __half g_wqHi [(long)QKVW * DMODEL];
__device__ __half g_woHi [(long)DMODEL * DMODEL];
__device__ __half g_qkvHi[(long)BATCH * SEQ * QKVW];
__device__ __half g_atHi [(long)BATCH * SEQ * DMODEL];

// ---------------------------------------------------------------------------
// helpers
// ---------------------------------------------------------------------------
__device__ __forceinline__ uint32_t smem_u32(const void* p) {
    uint32_t a;
    asm("{ .reg .u64 t; cvta.to.shared.u64 t, %1; cvt.u32.u64 %0, t; }"
        : "=r"(a) : "l"(p));
    return a;
}
__device__ __forceinline__ void cp16(uint32_t saddr, const void* g) {
    asm volatile("cp.async.cg.shared.global [%0], [%1], 16;" :: "r"(saddr), "l"(g));
}
#define CP_COMMIT() asm volatile("cp.async.commit_group;" ::: "memory")
#define CP_WAIT1()  asm volatile("cp.async.wait_group 1;" ::: "memory")
#define CP_WAIT0()  asm volatile("cp.async.wait_group 0;" ::: "memory")

__device__ __forceinline__ void ldsm_x4(uint32_t addr, uint32_t& r0, uint32_t& r1,
                                        uint32_t& r2, uint32_t& r3) {
    asm volatile("ldmatrix.sync.aligned.m8n8.x4.shared.b16 {%0,%1,%2,%3}, [%4];"
                 : "=r"(r0), "=r"(r1), "=r"(r2), "=r"(r3) : "r"(addr));
}
__device__ __forceinline__ void ldsm_x4t(uint32_t addr, uint32_t& r0, uint32_t& r1,
                                         uint32_t& r2, uint32_t& r3) {
    asm volatile("ldmatrix.sync.aligned.m8n8.x4.trans.shared.b16 {%0,%1,%2,%3}, [%4];"
                 : "=r"(r0), "=r"(r1), "=r"(r2), "=r"(r3) : "r"(addr));
}
__device__ __forceinline__ void mma_f16(float* c, const uint32_t* a, const uint32_t* b) {
    asm volatile(
        "mma.sync.aligned.m16n8k16.row.col.f32.f16.f16.f32 "
        "{%0,%1,%2,%3}, {%4,%5,%6,%7}, {%8,%9}, {%0,%1,%2,%3};"
        : "+f"(c[0]), "+f"(c[1]), "+f"(c[2]), "+f"(c[3])
        : "r"(a[0]), "r"(a[1]), "r"(a[2]), "r"(a[3]), "r"(b[0]), "r"(b[1]));
}
__device__ __forceinline__ uint32_t trunc2h(float v0, float v1) {
    __half2 t = __floats2half2_rn(v0, v1);   // single F2FP.PACK instruction
    return *(uint32_t*)&t;
}

// ---------------------------------------------------------------------------
// HMMA GEMM (pure fp16): C[m,n] = sum_k Ah[m,k] * Bh[n,k]  (NT)
// CTA tile 128x128, BK=64, 3-stage cp.async (1 sync/iter, prefetch at bottom).
// 8 warps (2x4), warp tile 64x32. 144B padded rows. 2 CTAs/SM.
// QSC: multiply q-tiles (blockIdx.x%3==0) by QS2 after bias (exp2 folding).
// ---------------------------------------------------------------------------
constexpr int ROWB_G  = 144;              // 64 fp16 = 128B data + 16B pad
constexpr int MAT_G   = 128 * ROWB_G;     // 18432
constexpr int STAGE_G = 2 * MAT_G;        // Ah, Bh = 36864
constexpr int SMEM_G  = 3 * STAGE_G;      // 110592

template<bool F16OUT, bool BIAS, bool QSC>
__global__ void __launch_bounds__(256, 2)
tc_gemm(const __half* __restrict__ aHi,
        const __half* __restrict__ bHi,
        const float* __restrict__ bias,
        float* __restrict__ cF,
        __half* __restrict__ cH,
        int K, int lda, int ldb, int ldc,
        long aOut, long aIn, long bOut, long bIn, long cOut, long cIn,
        int Hdiv, float alpha)
{
    extern __shared__ __align__(128) char smem[];
    const uint32_t sb = smem_u32(smem);
    const int tid  = threadIdx.x;
    const int wid  = tid >> 5, lane = tid & 31;

    const int z  = blockIdx.z;
    const int zb = z / Hdiv, zh = z % Hdiv;
    const size_t aoff = (size_t)zb * aOut + (size_t)zh * aIn + (size_t)blockIdx.y * 128 * lda;
    const size_t boff = (size_t)zb * bOut + (size_t)zh * bIn + (size_t)blockIdx.x * 128 * ldb;
    aHi += aoff; bHi += boff;

    const int l_piece = tid & 7;        // 16B piece within 128B row
    const int l_rbase = tid >> 3;       // row base; +32 per rep

    #define LOAD_STAGE(kt, slot)                                                  \
    do {                                                                          \
        const uint32_t s_ = sb + (slot) * STAGE_G;                                \
        const int kb_ = (kt) * 64;                                                \
        _Pragma("unroll")                                                         \
        for (int i_ = 0; i_ < 4; i_++) {                                          \
            const int row_ = l_rbase + i_ * 32;                                   \
            cp16(s_ + row_*ROWB_G + l_piece*16,                                   \
                 aHi + (size_t)row_*lda + kb_ + l_piece*8);                       \
            cp16(s_ + MAT_G + row_*ROWB_G + l_piece*16,                           \
                 bHi + (size_t)row_*ldb + kb_ + l_piece*8);                       \
        }                                                                         \
    } while (0)

    const int wm = (wid >> 2) * 64;
    const int wn = (wid & 3) * 32;

    const int sel    = lane >> 3;
    const int within = lane & 7;
    const uint32_t aBase = (uint32_t)((wm + within + (sel & 1) * 8) * ROWB_G + (sel >> 1) * 16);
    const uint32_t bBase = (uint32_t)(MAT_G + (wn + within + (sel >> 1) * 8) * ROWB_G + (sel & 1) * 16);

    float acc[4][4][4];
    #pragma unroll
    for (int i = 0; i < 4; i++)
        #pragma unroll
        for (int j = 0; j < 4; j++)
            #pragma unroll
            for (int r = 0; r < 4; r++)
                acc[i][j][r] = 0.f;

    const int nk = K >> 6;

    LOAD_STAGE(0, 0); CP_COMMIT();
    if (nk > 1) LOAD_STAGE(1, 1);
    CP_COMMIT();
    CP_WAIT1();
    __syncthreads();

    for (int kt = 0; kt < nk; ++kt) {
        const uint32_t sS = sb + (kt % 3) * STAGE_G;
        #pragma unroll
        for (int ks = 0; ks < 4; ks++) {
            uint32_t aH[4][4], bH[4][2];
            #pragma unroll
            for (int mt = 0; mt < 4; mt++) {
                uint32_t ad = sS + aBase + mt * (16 * ROWB_G) + ks * 32;
                ldsm_x4(ad, aH[mt][0], aH[mt][1], aH[mt][2], aH[mt][3]);
            }
            #pragma unroll
            for (int p = 0; p < 2; p++) {
                uint32_t bd = sS + bBase + p * (16 * ROWB_G) + ks * 32;
                ldsm_x4(bd, bH[2*p][0], bH[2*p][1], bH[2*p+1][0], bH[2*p+1][1]);
            }
            #pragma unroll
            for (int mt = 0; mt < 4; mt++)
                #pragma unroll
                for (int nt = 0; nt < 4; nt++)
                    mma_f16(acc[mt][nt], aH[mt], bH[nt]);
        }
        // slot (kt+2)%3 was fully consumed at iteration kt-1 -> safe now.
        if (kt + 2 < nk) LOAD_STAGE(kt + 2, (kt + 2) % 3);
        CP_COMMIT();
        CP_WAIT1();        // stage kt+1 resident
        __syncthreads();
    }

    const size_t coff = (size_t)zb * cOut + (size_t)zh * cIn;
    const int gr = blockIdx.y * 128 + wm + (lane >> 2);
    const int gc = blockIdx.x * 128 + wn + (lane & 3) * 2;
    const float ts = (QSC && (blockIdx.x % 3 == 0)) ? QS2 : 1.0f;

    #pragma unroll
    for (int mt = 0; mt < 4; mt++) {
        #pragma unroll
        for (int nt = 0; nt < 4; nt++) {
            const int col = gc + nt * 8;
            float b0 = 0.f, b1 = 0.f;
            if (BIAS) { b0 = bias[col]; b1 = bias[col + 1]; }
            #pragma unroll
            for (int half_ = 0; half_ < 2; half_++) {
                const int row = gr + mt * 16 + half_ * 8;
                float v0 = (acc[mt][nt][half_ * 2]     * alpha + b0) * ts;
                float v1 = (acc[mt][nt][half_ * 2 + 1] * alpha + b1) * ts;
                if (F16OUT) {
                    *(uint32_t*)(cH + coff + (size_t)row * ldc + col) = trunc2h(v0, v1);
                } else {
                    float2 v; v.x = v0; v.y = v1;
                    *(float2*)(cF + coff + (size_t)row * ldc + col) = v;
                }
            }
        }
    }
    #undef LOAD_STAGE
}

// ---------------------------------------------------------------------------
// Flash attention (pure fp16), 2 CTAs/SM: per CTA = (head z, 64 q-rows),
// 128 threads = 4 warps x 16 rows. Q pre-scaled by alpha*log2(e) -> bare exp2.
// V is read DIRECTLY from qkv [s][d] layout; PV uses ldmatrix.trans
// (no transpose kernel, no Vt buffer).
// SMEM: Q (4 d-chunks of 64 rows) + 3-slot PAIR ring.
//   K pair: 2 x (128 s-rows x 80B)   = 20480
//   V pair: 2 x (32 s-rows x 272B)   = 17408   (slot sized for max: 20480)
// ---------------------------------------------------------------------------
constexpr int ROWB    = 80;
constexpr int MAT_B   = 128 * ROWB;                // 10240: one 128x32 K chunk
constexpr int CHQ_B   = 64 * ROWB;                 // 5120:  one 64x32 Q chunk
constexpr int VROW    = 272;                       // 128 fp16 = 256B + 16B pad
constexpr int VCH_B   = 32 * VROW;                 // 8704: one 32x128 V chunk
constexpr int PAIR_B  = 2 * MAT_B;                 // 20480 (max of K/V pair)
constexpr int FQ_SZ   = 4 * CHQ_B;                 // 20480
constexpr int FSMEM   = FQ_SZ + 3 * PAIR_B;        // 81920 -> 2 CTAs/SM

// pair g: kt = g>>2, pr = g&3.  pr 0-1: K halves (d 0-63 / 64-127).
//                               pr 2-3: V key-chunk pairs.  slot = g%3.
__device__ __forceinline__ void flash_issue_pair(
    int g, uint32_t sbKV, int tid,
    const __half* kH, const __half* vS)
{
    const int kt = g >> 2, pr = g & 3;
    const uint32_t dst = sbKV + (g % 3) * PAIR_B;
    if (pr < 2) {
        const int lr0 = tid >> 2, lp0 = tid & 3;
        #pragma unroll
        for (int half = 0; half < 2; half++) {
            const int colb = (2 * pr + half) * 32 + lp0 * 8;
            const uint32_t d0 = dst + half * MAT_B;
            #pragma unroll
            for (int i = 0; i < 4; i++) {
                const int r = lr0 + i * 32;
                cp16(d0 + r*ROWB + lp0*16, kH + (size_t)(kt * 128 + r) * QKVW + colb);
            }
        }
    } else {
        // V chunks 2*(pr-2)+half: 32 s-rows x 256B from qkv [s][d]
        #pragma unroll
        for (int half = 0; half < 2; half++) {
            const int c = 2 * (pr - 2) + half;
            const uint32_t d0 = dst + half * VCH_B;
            #pragma unroll
            for (int i = 0; i < 4; i++) {
                const int idx = tid + i * 128;     // 0..511
                const int row = idx >> 4, pc = idx & 15;
                cp16(d0 + row*VROW + pc*16,
                     vS + (size_t)(kt * 128 + c * 32 + row) * QKVW + pc * 8);
            }
        }
    }
}

__global__ void __launch_bounds__(128, 2)
flash_kernel(const __half* __restrict__ qkH,
             __half* __restrict__ oH)
{
    extern __shared__ __align__(128) char smem[];
    const uint32_t sb = smem_u32(smem);
    const int tid  = threadIdx.x;
    const int wid  = tid >> 5, lane = tid & 31;
    const int qt   = blockIdx.x;
    const int z    = blockIdx.y;
    const int b    = z >> 4, h = z & 15;

    const __half* qH = qkH + (size_t)b * SEQ * QKVW + h * 384;
    const __half* kH = qH + 128;
    const __half* vS = qH + 256;        // v slice, native [s][d] layout

    const int lr0 = tid >> 2;      // 0..31
    const int lp0 = tid & 3;

    const int q0 = qt * 64;
    // ---- load Q (4 d-chunks of 64 rows) ----
    #pragma unroll
    for (int c = 0; c < 4; c++) {
        const uint32_t d0 = sb + c * CHQ_B;
        const int colb = c * 32 + lp0 * 8;
        #pragma unroll
        for (int i = 0; i < 2; i++) {
            const int r = lr0 + i * 32;
            cp16(d0 + r*ROWB + lp0*16, qH + (size_t)(q0 + r) * QKVW + colb);
        }
    }
    CP_COMMIT();
    flash_issue_pair(0, sb + FQ_SZ, tid, kH, vS); CP_COMMIT();
    flash_issue_pair(1, sb + FQ_SZ, tid, kH, vS); CP_COMMIT();

    const int sel    = lane >> 3;
    const int within = lane & 7;
    const uint32_t aOff  = (uint32_t)((wid * 16 + within + (sel & 1) * 8) * ROWB + (sel >> 1) * 16);
    const uint32_t bOffB = (uint32_t)((within + (sel >> 1) * 8) * ROWB + (sel & 1) * 16);
    // V trans-ldmatrix: rows = k (s-dim), cols = n (d-dim)
    const uint32_t bOffV = (uint32_t)((within + (sel & 1) * 8) * VROW + (sel >> 1) * 16);

    float o[16][4];
    #pragma unroll
    for (int i = 0; i < 16; i++)
        #pragma unroll
        for (int j = 0; j < 4; j++) o[i][j] = 0.f;
    float s[16][4];
    uint32_t pfH[8][4];
    float mA = -1e30f, mB = -1e30f, lA = 0.f, lB = 0.f;

    for (int kt = 0; kt < 16; ++kt) {
        #pragma unroll
        for (int pr = 0; pr < 4; ++pr) {
            const int g = kt * 4 + pr;

            if (pr == 2) {
                // ---- online softmax BEFORE the V-load wait (overlaps it) ----
                float mtA = -1e30f, mtB = -1e30f;
                #pragma unroll
                for (int nt = 0; nt < 16; nt++) {
                    mtA = fmaxf(mtA, fmaxf(s[nt][0], s[nt][1]));
                    mtB = fmaxf(mtB, fmaxf(s[nt][2], s[nt][3]));
                }
                mtA = fmaxf(mtA, __shfl_xor_sync(~0u, mtA, 1));
                mtA = fmaxf(mtA, __shfl_xor_sync(~0u, mtA, 2));
                mtB = fmaxf(mtB, __shfl_xor_sync(~0u, mtB, 1));
                mtB = fmaxf(mtB, __shfl_xor_sync(~0u, mtB, 2));
                const float mnA = fmaxf(mA, mtA);
                const float mnB = fmaxf(mB, mtB);
                const float fA = exp2f(mA - mnA);
                const float fB = exp2f(mB - mnB);
                #pragma unroll
                for (int nt = 0; nt < 16; nt++) {
                    o[nt][0] *= fA; o[nt][1] *= fA;
                    o[nt][2] *= fB; o[nt][3] *= fB;
                }
                float sA = 0.f, sB = 0.f;
                #pragma unroll
                for (int nt = 0; nt < 16; nt++) {
                    const float p0 = exp2f(s[nt][0] - mnA);
                    const float p1 = exp2f(s[nt][1] - mnA);
                    const float p2 = exp2f(s[nt][2] - mnB);
                    const float p3 = exp2f(s[nt][3] - mnB);
                    sA += p0 + p1; sB += p2 + p3;
                    const uint32_t h01 = trunc2h(p0, p1);
                    const uint32_t h23 = trunc2h(p2, p3);
                    const int kf = nt >> 1;
                    if ((nt & 1) == 0) {
                        pfH[kf][0] = h01; pfH[kf][1] = h23;
                    } else {
                        pfH[kf][2] = h01; pfH[kf][3] = h23;
                    }
                }
                sA += __shfl_xor_sync(~0u, sA, 1);
                sA += __shfl_xor_sync(~0u, sA, 2);
                sB += __shfl_xor_sync(~0u, sB, 1);
                sB += __shfl_xor_sync(~0u, sB, 2);
                lA = lA * fA + sA;
                lB = lB * fB + sB;
                mA = mnA; mB = mnB;
            }

            if (g + 1 < 64) { CP_WAIT1(); } else { CP_WAIT0(); }
            __syncthreads();
            if (g + 2 < 64) {
                flash_issue_pair(g + 2, sb + FQ_SZ, tid, kH, vS);
                CP_COMMIT();
            }
            const uint32_t slotB = sb + FQ_SZ + (g % 3) * PAIR_B;

            if (pr < 2) {
                // ---- S-phase: d-chunks 2*pr, 2*pr+1 ----
                if (pr == 0) {
                    #pragma unroll
                    for (int i = 0; i < 16; i++)
                        #pragma unroll
                        for (int j = 0; j < 4; j++) s[i][j] = 0.f;
                }
                #pragma unroll
                for (int half = 0; half < 2; half++) {
                    const uint32_t qc  = sb + (2 * pr + half) * CHQ_B;
                    const uint32_t kvc = slotB + half * MAT_B;
                    #pragma unroll
                    for (int ks = 0; ks < 2; ks++) {
                        uint32_t aH4[4];
                        ldsm_x4(qc + aOff + ks*32, aH4[0], aH4[1], aH4[2], aH4[3]);
                        #pragma unroll
                        for (int p = 0; p < 8; p++) {
                            uint32_t bh[4];
                            ldsm_x4(kvc + bOffB + p*(16*ROWB) + ks*32,
                                    bh[0], bh[1], bh[2], bh[3]);
                            mma_f16(s[2*p],   aH4, bh);
                            mma_f16(s[2*p+1], aH4, bh + 2);
                        }
                    }
                }
            } else {
                // ---- PV-phase: V chunks via ldmatrix.trans from [s][d] ----
                #pragma unroll
                for (int half = 0; half < 2; half++) {
                    const int c = 2 * (pr - 2) + half;
                    const uint32_t kvc = slotB + half * VCH_B;
                    #pragma unroll
                    for (int ks = 0; ks < 2; ks++) {
                        const int kf = 2 * c + ks;
                        #pragma unroll
                        for (int p = 0; p < 8; p++) {
                            uint32_t bh[4];
                            ldsm_x4t(kvc + bOffV + ks*(16*VROW) + p*32,
                                     bh[0], bh[1], bh[2], bh[3]);
                            mma_f16(o[2*p],   pfH[kf], bh);
                            mma_f16(o[2*p+1], pfH[kf], bh + 2);
                        }
                    }
                }
            }
        }
    }

    const float invA = 1.f / lA;
    const float invB = 1.f / lB;
    const size_t rowA = (size_t)b * SEQ + q0 + wid * 16 + (lane >> 2);
    const size_t baseA = rowA * DMODEL + h * 128 + (lane & 3) * 2;
    const size_t baseB = baseA + (size_t)8 * DMODEL;
    #pragma unroll
    for (int nt = 0; nt < 16; nt++) {
        *(uint32_t*)(oH + baseA + nt * 8) = trunc2h(o[nt][0] * invA, o[nt][1] * invA);
        *(uint32_t*)(oH + baseB + nt * 8) = trunc2h(o[nt][2] * invB, o[nt][3] * invB);
    }
}

// ---------------------------------------------------------------------------
// fp32 -> fp16 truncate (elementwise, float4)
// ---------------------------------------------------------------------------
__global__ void __launch_bounds__(256)
trunc_kernel(const float* __restrict__ in, __half* __restrict__ hi)
{
    const long i = (long)blockIdx.x * 256 + threadIdx.x;
    float4 v = ((const float4*)in)[i];
    ((uint32_t*)hi)[i * 2]     = trunc2h(v.x, v.y);
    ((uint32_t*)hi)[i * 2 + 1] = trunc2h(v.z, v.w);
}

// ---------------------------------------------------------------------------
extern "C" void kernel_launch(void* const* d_in, const int* in_sizes, int n_in,
                              void* d_out, int out_size)
{
    const float* x     = (const float*)d_in[0];
    const float* w_qkv = (const float*)d_in[2];
    const float* b_qkv = (const float*)d_in[3];
    const float* w_o   = (const float*)d_in[4];
    const float* b_o   = (const float*)d_in[5];
    float* out = (float*)d_out;

    __half *xsH, *wqH, *woH, *qkH, *atH;
    cudaGetSymbolAddress((void**)&xsH, g_xsHi);
    cudaGetSymbolAddress((void**)&wqH, g_wqHi);
    cudaGetSymbolAddress((void**)&woH, g_woHi);
    cudaGetSymbolAddress((void**)&qkH, g_qkvHi);
    cudaGetSymbolAddress((void**)&atH, g_atHi);

    cudaFuncSetAttribute(tc_gemm<true,  true, true >, cudaFuncAttributeMaxDynamicSharedMemorySize, SMEM_G);
    cudaFuncSetAttribute(tc_gemm<false, true, false>, cudaFuncAttributeMaxDynamicSharedMemorySize, SMEM_G);
    cudaFuncSetAttribute(flash_kernel, cudaFuncAttributeMaxDynamicSharedMemorySize, FSMEM);

    // 0) truncate inputs to fp16
    trunc_kernel<<<(long)BATCH*SEQ*DMODEL/1024, 256>>>(x,     xsH);
    trunc_kernel<<<(long)QKVW*DMODEL/1024,      256>>>(w_qkv, wqH);
    trunc_kernel<<<(long)DMODEL*DMODEL/1024,    256>>>(w_o,   woH);

    // 1) QKV projection -> qkv fp16 (bias fused; q-tiles pre-scaled by QS2)
    {
        dim3 grid(QKVW / 128, (BATCH * SEQ) / 128, 1);
        tc_gemm<true, true, true><<<grid, 256, SMEM_G>>>(
            xsH, wqH, b_qkv, nullptr, qkH,
            DMODEL, DMODEL, DMODEL, QKVW,
            0, 0, 0, 0, 0, 0, 1, 1.0f);
    }

    // 2) fused flash attention -> attn fp16  (64 q-rows per CTA, 2 CTAs/SM)
    flash_kernel<<<dim3(SEQ / 64, BH), 128, FSMEM>>>(qkH, atH);

    // 3) output projection (bias fused) -> out fp32
    {
        dim3 grid(DMODEL / 128, (BATCH * SEQ) / 128, 1);
        tc_gemm<false, true, false><<<grid, 256, SMEM_G>>>(
            atH, woH, b_o, out, nullptr,
            DMODEL, DMODEL, DMODEL, DMODEL,
            0, 0, 0, 0, 0, 0, 1, 1.0f);
    }
}